// round 2
// baseline (speedup 1.0000x reference)
#include <cuda_runtime.h>

#define IN_DIM 128
#define HIDD   128
#define OUTD   40
#define MAXN   50000
#define MAXE   800000

// ---------------- scratch (device globals: allocation-free) ----------------
static __device__ float g_yw[MAXN * HIDD];    // dinv * (x @ W1)
static __device__ float g_h [MAXN * HIDD];    // layer-1 output (post ReLU)
static __device__ float g_ow[MAXN * OUTD];    // dinv * (h @ W2)
static __device__ int   g_degi[MAXN];         // edge in-degree (no self loop)
static __device__ float g_dinv[MAXN];
static __device__ int   g_rs  [MAXN + 1];     // CSR row starts
static __device__ int   g_cur [MAXN];         // scatter cursors
static __device__ int   g_col [MAXE];         // CSR column (src) indices
static __device__ int   g_is64;               // edge_index dtype flag

// ---------------- edge-index dtype detection ----------------
// int64 edge values < 2^31 have zero hi-words at odd 32-bit positions.
__global__ void detect_kernel(const int* __restrict__ ei, int twoE) {
    __shared__ int s_any;
    if (threadIdx.x == 0) s_any = 0;
    __syncthreads();
    int lim = twoE < 8192 ? twoE : 8192;
    for (int i = 1 + 2 * (int)threadIdx.x; i < lim; i += 2 * (int)blockDim.x)
        if (ei[i] != 0) s_any = 1;
    __syncthreads();
    if (threadIdx.x == 0) g_is64 = (s_any == 0) ? 1 : 0;
}

__device__ __forceinline__ int get_idx(const void* ei, long long pos, int is64) {
    return is64 ? (int)((const long long*)ei)[pos] : ((const int*)ei)[pos];
}

// ---------------- degree histogram ----------------
__global__ void zero_deg_kernel(int N) {
    int i = blockIdx.x * blockDim.x + threadIdx.x;
    if (i < N) g_degi[i] = 0;
}

__global__ void deg_kernel(const void* __restrict__ ei, int E) {
    int e = blockIdx.x * blockDim.x + threadIdx.x;
    if (e >= E) return;
    int d = get_idx(ei, (long long)E + e, g_is64);
    atomicAdd(&g_degi[d], 1);
}

// ---------------- single-block exclusive scan + dinv ----------------
__global__ void scan_kernel(int N, int E) {
    const int T = 1024;
    int t = threadIdx.x;
    int chunk = (N + T - 1) / T;
    int lo = t * chunk, hi = lo + chunk; if (hi > N) hi = N;
    int sum = 0;
    for (int i = lo; i < hi; i++) sum += g_degi[i];

    __shared__ int warpsum[32];
    int lane = t & 31, wid = t >> 5;
    int v = sum;
#pragma unroll
    for (int o = 1; o < 32; o <<= 1) {
        int u = __shfl_up_sync(0xffffffffu, v, o);
        if (lane >= o) v += u;
    }
    if (lane == 31) warpsum[wid] = v;
    __syncthreads();
    if (wid == 0) {
        int w = warpsum[lane];
#pragma unroll
        for (int o = 1; o < 32; o <<= 1) {
            int u = __shfl_up_sync(0xffffffffu, w, o);
            if (lane >= o) w += u;
        }
        warpsum[lane] = w;
    }
    __syncthreads();
    int run = v - sum + (wid > 0 ? warpsum[wid - 1] : 0);  // exclusive prefix
    for (int i = lo; i < hi; i++) {
        g_rs[i]  = run;
        g_cur[i] = run;
        g_dinv[i] = rsqrtf((float)(g_degi[i] + 1));   // +1 self loop; deg>0 always
        run += g_degi[i];
    }
    if (t == 0) g_rs[N] = E;
}

// ---------------- scatter: build CSR column array ----------------
__global__ void scatter_kernel(const void* __restrict__ ei, int E) {
    int e = blockIdx.x * blockDim.x + threadIdx.x;
    if (e >= E) return;
    int is64 = g_is64;
    int s = get_idx(ei, e, is64);
    int d = get_idx(ei, (long long)E + e, is64);
    int pos = atomicAdd(&g_cur[d], 1);
    g_col[pos] = s;
}

// ---------------- tiled fp32 GEMM with fused row-scale: C = dinv[r]*(A@B) ----
template <int BM, int BN, int BK, int TM, int TN>
__global__ void gemm_kernel(const float* __restrict__ A,
                            const float* __restrict__ B,
                            float* __restrict__ C, int M, int K) {
    constexpr int NT  = (BM / TM) * (BN / TN);
    constexpr int LDA = BM + 4;
    __shared__ float As[BK * LDA];   // transposed: As[k][row]
    __shared__ float Bs[BK * BN];    // Bs[k][col]

    const int tid = threadIdx.x;
    const int tx  = tid % (BN / TN);
    const int ty  = tid / (BN / TN);
    const int row0 = blockIdx.x * BM;

    float acc[TM][TN];
#pragma unroll
    for (int i = 0; i < TM; i++)
#pragma unroll
        for (int j = 0; j < TN; j++) acc[i][j] = 0.0f;

    for (int k0 = 0; k0 < K; k0 += BK) {
        for (int idx = tid; idx < BM * BK; idx += NT) {
            int r = idx / BK, kk = idx % BK;
            int gr = row0 + r;
            As[kk * LDA + r] = (gr < M) ? A[(size_t)gr * K + k0 + kk] : 0.0f;
        }
        for (int idx = tid; idx < BK * BN; idx += NT) {
            int kk = idx / BN, c = idx % BN;
            Bs[kk * BN + c] = B[(size_t)(k0 + kk) * BN + c];
        }
        __syncthreads();
#pragma unroll
        for (int kk = 0; kk < BK; kk++) {
            float a[TM], b[TN];
#pragma unroll
            for (int i = 0; i < TM; i++) a[i] = As[kk * LDA + ty * TM + i];
#pragma unroll
            for (int j = 0; j < TN; j++) b[j] = Bs[kk * BN + tx * TN + j];
#pragma unroll
            for (int i = 0; i < TM; i++)
#pragma unroll
                for (int j = 0; j < TN; j++) acc[i][j] += a[i] * b[j];
        }
        __syncthreads();
    }

#pragma unroll
    for (int i = 0; i < TM; i++) {
        int gr = row0 + ty * TM + i;
        if (gr < M) {
            float di = g_dinv[gr];
#pragma unroll
            for (int j = 0; j < TN; j++)
                C[(size_t)gr * BN + tx * TN + j] = acc[i][j] * di;
        }
    }
}

// ---------------- layer-1 aggregation (warp per node, fused self+bias+ReLU) --
// h[d] = relu( dinv[d] * ( sum_{src in nbr(d)} yw[src] + yw[d] ) + b1 )
__global__ void __launch_bounds__(256) agg1_kernel(const float* __restrict__ b1, int N) {
    int warp = (blockIdx.x * blockDim.x + threadIdx.x) >> 5;
    int lane = threadIdx.x & 31;
    if (warp >= N) return;
    int d = warp;
    const float4* __restrict__ yw4 = (const float4*)g_yw;

    float4 acc = yw4[(size_t)d * 32 + lane];     // self-loop term (pre-scaled)
    int s0 = g_rs[d], s1 = g_rs[d + 1];
    for (int base = s0; base < s1; base += 32) {
        int n = s1 - base; if (n > 32) n = 32;
        int c = (lane < n) ? g_col[base + lane] : 0;
#pragma unroll 4
        for (int j = 0; j < n; j++) {
            int s = __shfl_sync(0xffffffffu, c, j);
            float4 v = yw4[(size_t)s * 32 + lane];
            acc.x += v.x; acc.y += v.y; acc.z += v.z; acc.w += v.w;
        }
    }
    float di = g_dinv[d];
    float4 bb = ((const float4*)b1)[lane];
    float4 o;
    o.x = fmaxf(acc.x * di + bb.x, 0.0f);
    o.y = fmaxf(acc.y * di + bb.y, 0.0f);
    o.z = fmaxf(acc.z * di + bb.z, 0.0f);
    o.w = fmaxf(acc.w * di + bb.w, 0.0f);
    ((float4*)g_h)[(size_t)d * 32 + lane] = o;
}

// ---------------- layer-2 aggregation + bias + softmax (warp per node) ------
// logits = dinv[d] * (sum ow[src] + ow[d]) + b2 ; out = softmax(logits)
__global__ void __launch_bounds__(256) agg2_kernel(float* __restrict__ out,
                                                   const float* __restrict__ b2, int N) {
    int warp = (blockIdx.x * blockDim.x + threadIdx.x) >> 5;
    int lane = threadIdx.x & 31;
    if (warp >= N) return;
    int d = warp;
    const float* __restrict__ ow = g_ow;

    float a0 = ow[(size_t)d * OUTD + lane];                         // cols 0..31
    float a1 = (lane < 8) ? ow[(size_t)d * OUTD + 32 + lane] : 0.0f; // cols 32..39
    int s0 = g_rs[d], s1 = g_rs[d + 1];
    for (int base = s0; base < s1; base += 32) {
        int n = s1 - base; if (n > 32) n = 32;
        int c = (lane < n) ? g_col[base + lane] : 0;
#pragma unroll 4
        for (int j = 0; j < n; j++) {
            int s = __shfl_sync(0xffffffffu, c, j);
            a0 += ow[(size_t)s * OUTD + lane];
            if (lane < 8) a1 += ow[(size_t)s * OUTD + 32 + lane];
        }
    }
    float di = g_dinv[d];
    float l0 = a0 * di + b2[lane];
    float l1 = (lane < 8) ? (a1 * di + b2[32 + lane]) : -1e30f;

    float m = fmaxf(l0, l1);
#pragma unroll
    for (int o = 16; o > 0; o >>= 1)
        m = fmaxf(m, __shfl_xor_sync(0xffffffffu, m, o));
    float e0 = __expf(l0 - m);
    float e1 = (lane < 8) ? __expf(l1 - m) : 0.0f;
    float s = e0 + e1;
#pragma unroll
    for (int o = 16; o > 0; o >>= 1)
        s += __shfl_xor_sync(0xffffffffu, s, o);
    float inv = 1.0f / s;
    out[(size_t)d * OUTD + lane] = e0 * inv;
    if (lane < 8) out[(size_t)d * OUTD + 32 + lane] = e1 * inv;
}

// ---------------- launch ----------------
extern "C" void kernel_launch(void* const* d_in, const int* in_sizes, int n_in,
                              void* d_out, int out_size) {
    const float* x  = (const float*)d_in[0];
    const void*  ei = d_in[1];
    const float* W1 = (const float*)d_in[2];
    const float* b1 = (const float*)d_in[3];
    const float* W2 = (const float*)d_in[4];
    const float* b2 = (const float*)d_in[5];
    float* out = (float*)d_out;

    int N = in_sizes[0] / IN_DIM;
    int E = in_sizes[1] / 2;

    float *yw, *h, *ow;
    cudaGetSymbolAddress((void**)&yw, g_yw);
    cudaGetSymbolAddress((void**)&h,  g_h);
    cudaGetSymbolAddress((void**)&ow, g_ow);

    // CSR build
    detect_kernel<<<1, 256>>>((const int*)ei, 2 * E);
    zero_deg_kernel<<<(N + 255) / 256, 256>>>(N);
    deg_kernel<<<(E + 255) / 256, 256>>>(ei, E);
    scan_kernel<<<1, 1024>>>(N, E);
    scatter_kernel<<<(E + 255) / 256, 256>>>(ei, E);

    // layer 1
    gemm_kernel<128, 128, 16, 8, 8><<<(N + 127) / 128, 256>>>(x, W1, yw, N, IN_DIM);
    agg1_kernel<<<(N * 32 + 255) / 256, 256>>>(b1, N);

    // layer 2
    gemm_kernel<128, 40, 16, 8, 5><<<(N + 127) / 128, 128>>>(h, W2, ow, N, HIDD);
    agg2_kernel<<<(N * 32 + 255) / 256, 256>>>(out, b2, N);
}

// round 4
// speedup vs baseline: 1.4125x; 1.4125x over previous
#include <cuda_runtime.h>

#define IN_DIM 128
#define HIDD   128
#define OUTD   40
#define MAXN   50000
#define MAXE   800000
#define SCAN_B 256

// ---------------- scratch (device globals: allocation-free) ----------------
static __device__ float g_yw[MAXN * HIDD];    // dinv * (x @ W1)
static __device__ float g_h [MAXN * HIDD];    // layer-1 output (post ReLU)
static __device__ float g_ow[MAXN * OUTD];    // dinv * (h @ W2)
static __device__ int   g_degi[MAXN];         // edge in-degree (no self loop)
static __device__ float g_dinv[MAXN];
static __device__ int   g_rs  [MAXN + 1];     // CSR row starts
static __device__ int   g_cur [MAXN];         // scatter cursors
static __device__ int   g_col [MAXE];         // CSR column (src) indices
static __device__ int   g_bsum[(MAXN + SCAN_B - 1) / SCAN_B + 1];
static __device__ int   g_is64;               // edge_index dtype flag

// ---------------- edge-index dtype detection ----------------
__global__ void detect_kernel(const int* __restrict__ ei, int twoE) {
    __shared__ int s_any;
    if (threadIdx.x == 0) s_any = 0;
    __syncthreads();
    int lim = twoE < 8192 ? twoE : 8192;
    for (int i = 1 + 2 * (int)threadIdx.x; i < lim; i += 2 * (int)blockDim.x)
        if (ei[i] != 0) s_any = 1;
    __syncthreads();
    if (threadIdx.x == 0) g_is64 = (s_any == 0) ? 1 : 0;
}

__device__ __forceinline__ int get_idx(const void* ei, long long pos, int is64) {
    return is64 ? (int)((const long long*)ei)[pos] : ((const int*)ei)[pos];
}

// ---------------- degree histogram ----------------
__global__ void zero_deg_kernel(int N) {
    int i = blockIdx.x * blockDim.x + threadIdx.x;
    if (i < N) g_degi[i] = 0;
}

__global__ void deg_kernel(const void* __restrict__ ei, int E) {
    int e = blockIdx.x * blockDim.x + threadIdx.x;
    if (e >= E) return;
    int d = get_idx(ei, (long long)E + e, g_is64);
    atomicAdd(&g_degi[d], 1);
}

// ---------------- parallel 3-phase exclusive scan ----------------
// Phase 1: per-block sums of degrees.
__global__ void scan_p1_kernel(int N) {
    int i = blockIdx.x * blockDim.x + threadIdx.x;
    int v = (i < N) ? g_degi[i] : 0;
    int lane = threadIdx.x & 31, wid = threadIdx.x >> 5;
#pragma unroll
    for (int o = 16; o > 0; o >>= 1) v += __shfl_xor_sync(0xffffffffu, v, o);
    __shared__ int ws[SCAN_B / 32];
    if (lane == 0) ws[wid] = v;
    __syncthreads();
    if (threadIdx.x == 0) {
        int s = 0;
#pragma unroll
        for (int w = 0; w < SCAN_B / 32; w++) s += ws[w];
        g_bsum[blockIdx.x] = s;
    }
}

// Phase 2: single block (all 32 lanes of each warp active in every shfl).
__global__ void scan_p2_kernel(int nb) {
    int t = threadIdx.x;
    int v = (t < nb) ? g_bsum[t] : 0;
    int lane = t & 31, wid = t >> 5;
    int x = v;
#pragma unroll
    for (int o = 1; o < 32; o <<= 1) {
        int u = __shfl_up_sync(0xffffffffu, x, o);
        if (lane >= o) x += u;
    }
    __shared__ int ws[32];
    if (lane == 31) ws[wid] = x;
    __syncthreads();
    if (wid == 0) {                       // full warp active
        int w = ws[lane];
#pragma unroll
        for (int o = 1; o < 32; o <<= 1) {
            int u = __shfl_up_sync(0xffffffffu, w, o);
            if (lane >= o) w += u;
        }
        ws[lane] = w;
    }
    __syncthreads();
    int excl = x - v + (wid > 0 ? ws[wid - 1] : 0);
    if (t < nb) g_bsum[t] = excl;
}

// Phase 3: per-block exclusive scan + block offset; write rs/cur/dinv.
// FIX vs prior round: warp-sum scan runs with ALL 32 lanes of warp 0 active
// (zero-padded ws[32]) — no divergent __shfl_up_sync.
__global__ void scan_p3_kernel(int N, int E) {
    int i = blockIdx.x * blockDim.x + threadIdx.x;
    int v = (i < N) ? g_degi[i] : 0;
    int lane = threadIdx.x & 31, wid = threadIdx.x >> 5;

    __shared__ int ws[32];
    if (threadIdx.x < 32) ws[threadIdx.x] = 0;
    __syncthreads();

    int x = v;
#pragma unroll
    for (int o = 1; o < 32; o <<= 1) {
        int u = __shfl_up_sync(0xffffffffu, x, o);
        if (lane >= o) x += u;
    }
    if (lane == 31) ws[wid] = x;
    __syncthreads();
    if (wid == 0) {                       // full warp active, extras scan zeros
        int w = ws[lane];
#pragma unroll
        for (int o = 1; o < 32; o <<= 1) {
            int u = __shfl_up_sync(0xffffffffu, w, o);
            if (lane >= o) w += u;
        }
        ws[lane] = w;
    }
    __syncthreads();
    int excl = x - v + (wid > 0 ? ws[wid - 1] : 0) + g_bsum[blockIdx.x];
    if (i < N) {
        g_rs[i]  = excl;
        g_cur[i] = excl;
        g_dinv[i] = rsqrtf((float)(v + 1));   // +1 self loop
    }
    if (i == 0) g_rs[N] = E;
}

// ---------------- scatter: build CSR column array ----------------
__global__ void scatter_kernel(const void* __restrict__ ei, int E) {
    int e = blockIdx.x * blockDim.x + threadIdx.x;
    if (e >= E) return;
    int is64 = g_is64;
    int s = get_idx(ei, e, is64);
    int d = get_idx(ei, (long long)E + e, is64);
    int pos = atomicAdd(&g_cur[d], 1);
    g_col[pos] = s;
}

// ---------------- tiled fp32 GEMM with fused row-scale: C = dinv[r]*(A@B) ----
template <int BM, int BN, int BK, int TM, int TN>
__global__ void gemm_kernel(const float* __restrict__ A,
                            const float* __restrict__ B,
                            float* __restrict__ C, int M, int K) {
    constexpr int NT  = (BM / TM) * (BN / TN);
    constexpr int LDA = BM + 4;
    __shared__ float As[BK * LDA];   // transposed: As[k][row]
    __shared__ float Bs[BK * BN];    // Bs[k][col]

    const int tid = threadIdx.x;
    const int tx  = tid % (BN / TN);
    const int ty  = tid / (BN / TN);
    const int row0 = blockIdx.x * BM;

    float acc[TM][TN];
#pragma unroll
    for (int i = 0; i < TM; i++)
#pragma unroll
        for (int j = 0; j < TN; j++) acc[i][j] = 0.0f;

    for (int k0 = 0; k0 < K; k0 += BK) {
        for (int idx = tid; idx < BM * BK; idx += NT) {
            int r = idx / BK, kk = idx % BK;
            int gr = row0 + r;
            As[kk * LDA + r] = (gr < M) ? A[(size_t)gr * K + k0 + kk] : 0.0f;
        }
        for (int idx = tid; idx < BK * BN; idx += NT) {
            int kk = idx / BN, c = idx % BN;
            Bs[kk * BN + c] = B[(size_t)(k0 + kk) * BN + c];
        }
        __syncthreads();
#pragma unroll
        for (int kk = 0; kk < BK; kk++) {
            float a[TM], b[TN];
#pragma unroll
            for (int i = 0; i < TM; i++) a[i] = As[kk * LDA + ty * TM + i];
#pragma unroll
            for (int j = 0; j < TN; j++) b[j] = Bs[kk * BN + tx * TN + j];
#pragma unroll
            for (int i = 0; i < TM; i++)
#pragma unroll
                for (int j = 0; j < TN; j++) acc[i][j] += a[i] * b[j];
        }
        __syncthreads();
    }

#pragma unroll
    for (int i = 0; i < TM; i++) {
        int gr = row0 + ty * TM + i;
        if (gr < M) {
            float di = g_dinv[gr];
#pragma unroll
            for (int j = 0; j < TN; j++)
                C[(size_t)gr * BN + tx * TN + j] = acc[i][j] * di;
        }
    }
}

// ---------------- layer-1 aggregation (warp per node, fused self+bias+ReLU) --
__global__ void __launch_bounds__(256) agg1_kernel(const float* __restrict__ b1, int N) {
    int warp = (blockIdx.x * blockDim.x + threadIdx.x) >> 5;
    int lane = threadIdx.x & 31;
    if (warp >= N) return;
    int d = warp;
    const float4* __restrict__ yw4 = (const float4*)g_yw;

    float4 acc = yw4[(size_t)d * 32 + lane];     // self-loop term (pre-scaled)
    int s0 = g_rs[d], s1 = g_rs[d + 1];
    for (int base = s0; base < s1; base += 32) {
        int n = s1 - base; if (n > 32) n = 32;
        int c = (lane < n) ? g_col[base + lane] : 0;
#pragma unroll 4
        for (int j = 0; j < n; j++) {
            int s = __shfl_sync(0xffffffffu, c, j);
            float4 v = yw4[(size_t)s * 32 + lane];
            acc.x += v.x; acc.y += v.y; acc.z += v.z; acc.w += v.w;
        }
    }
    float di = g_dinv[d];
    float4 bb = ((const float4*)b1)[lane];
    float4 o;
    o.x = fmaxf(acc.x * di + bb.x, 0.0f);
    o.y = fmaxf(acc.y * di + bb.y, 0.0f);
    o.z = fmaxf(acc.z * di + bb.z, 0.0f);
    o.w = fmaxf(acc.w * di + bb.w, 0.0f);
    ((float4*)g_h)[(size_t)d * 32 + lane] = o;
}

// ---------------- layer-2 aggregation + bias + softmax (warp per node) ------
__global__ void __launch_bounds__(256) agg2_kernel(float* __restrict__ out,
                                                   const float* __restrict__ b2, int N) {
    int warp = (blockIdx.x * blockDim.x + threadIdx.x) >> 5;
    int lane = threadIdx.x & 31;
    if (warp >= N) return;
    int d = warp;
    const float* __restrict__ ow = g_ow;

    float a0 = ow[(size_t)d * OUTD + lane];
    float a1 = (lane < 8) ? ow[(size_t)d * OUTD + 32 + lane] : 0.0f;
    int s0 = g_rs[d], s1 = g_rs[d + 1];
    for (int base = s0; base < s1; base += 32) {
        int n = s1 - base; if (n > 32) n = 32;
        int c = (lane < n) ? g_col[base + lane] : 0;
#pragma unroll 4
        for (int j = 0; j < n; j++) {
            int s = __shfl_sync(0xffffffffu, c, j);
            a0 += ow[(size_t)s * OUTD + lane];
            if (lane < 8) a1 += ow[(size_t)s * OUTD + 32 + lane];
        }
    }
    float di = g_dinv[d];
    float l0 = a0 * di + b2[lane];
    float l1 = (lane < 8) ? (a1 * di + b2[32 + lane]) : -1e30f;

    float m = fmaxf(l0, l1);
#pragma unroll
    for (int o = 16; o > 0; o >>= 1)
        m = fmaxf(m, __shfl_xor_sync(0xffffffffu, m, o));
    float e0 = __expf(l0 - m);
    float e1 = (lane < 8) ? __expf(l1 - m) : 0.0f;
    float s = e0 + e1;
#pragma unroll
    for (int o = 16; o > 0; o >>= 1)
        s += __shfl_xor_sync(0xffffffffu, s, o);
    float inv = 1.0f / s;
    out[(size_t)d * OUTD + lane] = e0 * inv;
    if (lane < 8) out[(size_t)d * OUTD + 32 + lane] = e1 * inv;
}

// ---------------- launch ----------------
extern "C" void kernel_launch(void* const* d_in, const int* in_sizes, int n_in,
                              void* d_out, int out_size) {
    const float* x  = (const float*)d_in[0];
    const void*  ei = d_in[1];
    const float* W1 = (const float*)d_in[2];
    const float* b1 = (const float*)d_in[3];
    const float* W2 = (const float*)d_in[4];
    const float* b2 = (const float*)d_in[5];
    float* out = (float*)d_out;

    int N = in_sizes[0] / IN_DIM;
    int E = in_sizes[1] / 2;
    int nb = (N + SCAN_B - 1) / SCAN_B;

    float *yw, *h, *ow;
    cudaGetSymbolAddress((void**)&yw, g_yw);
    cudaGetSymbolAddress((void**)&h,  g_h);
    cudaGetSymbolAddress((void**)&ow, g_ow);

    // CSR build (parallel scan)
    detect_kernel<<<1, 256>>>((const int*)ei, 2 * E);
    zero_deg_kernel<<<(N + 255) / 256, 256>>>(N);
    deg_kernel<<<(E + 255) / 256, 256>>>(ei, E);
    scan_p1_kernel<<<nb, SCAN_B>>>(N);
    scan_p2_kernel<<<1, 1024>>>(nb);
    scan_p3_kernel<<<nb, SCAN_B>>>(N, E);
    scatter_kernel<<<(E + 255) / 256, 256>>>(ei, E);

    // layer 1
    gemm_kernel<128, 128, 16, 8, 8><<<(N + 127) / 128, 256>>>(x, W1, yw, N, IN_DIM);
    agg1_kernel<<<(N * 32 + 255) / 256, 256>>>(b1, N);

    // layer 2
    gemm_kernel<128, 40, 16, 8, 5><<<(N + 127) / 128, 128>>>(h, W2, ow, N, HIDD);
    agg2_kernel<<<(N * 32 + 255) / 256, 256>>>(out, b2, N);
}

// round 5
// speedup vs baseline: 1.4523x; 1.0282x over previous
#include <cuda_runtime.h>

#define IN_DIM 128
#define HIDD   128
#define OUTD   40
#define MAXN   50000
#define MAXE   800000
#define SCAN_B 256

// ---------------- scratch (device globals: allocation-free) ----------------
static __device__ float g_yw[MAXN * HIDD];    // dinv * (x @ W1)
static __device__ float g_h [MAXN * HIDD];    // layer-1 output (post ReLU)
static __device__ float g_ow[MAXN * OUTD];    // dinv * (h @ W2)
static __device__ int   g_degi[MAXN];         // edge in-degree (no self loop)
static __device__ float g_dinv[MAXN];
static __device__ int   g_rs  [MAXN + 1];     // CSR row starts
static __device__ int   g_cur [MAXN];         // scatter cursors
static __device__ int   g_col [MAXE];         // CSR column (src) indices
static __device__ int   g_bsum[(MAXN + SCAN_B - 1) / SCAN_B + 1];
static __device__ int   g_is64;               // edge_index dtype flag

// ---------------- fused: dtype detection (block 0) + zero degrees ----------
__global__ void detzero_kernel(const int* __restrict__ ei, int twoE, int N) {
    int i = blockIdx.x * blockDim.x + threadIdx.x;
    if (i < N) g_degi[i] = 0;
    if (blockIdx.x == 0) {
        __shared__ int s_any;
        if (threadIdx.x == 0) s_any = 0;
        __syncthreads();
        int lim = twoE < 8192 ? twoE : 8192;
        for (int k = 1 + 2 * (int)threadIdx.x; k < lim; k += 2 * (int)blockDim.x)
            if (ei[k] != 0) s_any = 1;
        __syncthreads();
        if (threadIdx.x == 0) g_is64 = (s_any == 0) ? 1 : 0;
    }
}

__device__ __forceinline__ int get_idx(const void* ei, long long pos, int is64) {
    return is64 ? (int)((const long long*)ei)[pos] : ((const int*)ei)[pos];
}

// ---------------- degree histogram ----------------
__global__ void deg_kernel(const void* __restrict__ ei, int E) {
    int e = blockIdx.x * blockDim.x + threadIdx.x;
    if (e >= E) return;
    int d = get_idx(ei, (long long)E + e, g_is64);
    atomicAdd(&g_degi[d], 1);
}

// ---------------- parallel 3-phase exclusive scan ----------------
__global__ void scan_p1_kernel(int N) {
    int i = blockIdx.x * blockDim.x + threadIdx.x;
    int v = (i < N) ? g_degi[i] : 0;
    int lane = threadIdx.x & 31, wid = threadIdx.x >> 5;
#pragma unroll
    for (int o = 16; o > 0; o >>= 1) v += __shfl_xor_sync(0xffffffffu, v, o);
    __shared__ int ws[SCAN_B / 32];
    if (lane == 0) ws[wid] = v;
    __syncthreads();
    if (threadIdx.x == 0) {
        int s = 0;
#pragma unroll
        for (int w = 0; w < SCAN_B / 32; w++) s += ws[w];
        g_bsum[blockIdx.x] = s;
    }
}

__global__ void scan_p2_kernel(int nb) {
    int t = threadIdx.x;
    int v = (t < nb) ? g_bsum[t] : 0;
    int lane = t & 31, wid = t >> 5;
    int x = v;
#pragma unroll
    for (int o = 1; o < 32; o <<= 1) {
        int u = __shfl_up_sync(0xffffffffu, x, o);
        if (lane >= o) x += u;
    }
    __shared__ int ws[32];
    if (lane == 31) ws[wid] = x;
    __syncthreads();
    if (wid == 0) {
        int w = ws[lane];
#pragma unroll
        for (int o = 1; o < 32; o <<= 1) {
            int u = __shfl_up_sync(0xffffffffu, w, o);
            if (lane >= o) w += u;
        }
        ws[lane] = w;
    }
    __syncthreads();
    int excl = x - v + (wid > 0 ? ws[wid - 1] : 0);
    if (t < nb) g_bsum[t] = excl;
}

__global__ void scan_p3_kernel(int N, int E) {
    int i = blockIdx.x * blockDim.x + threadIdx.x;
    int v = (i < N) ? g_degi[i] : 0;
    int lane = threadIdx.x & 31, wid = threadIdx.x >> 5;

    __shared__ int ws[32];
    if (threadIdx.x < 32) ws[threadIdx.x] = 0;
    __syncthreads();

    int x = v;
#pragma unroll
    for (int o = 1; o < 32; o <<= 1) {
        int u = __shfl_up_sync(0xffffffffu, x, o);
        if (lane >= o) x += u;
    }
    if (lane == 31) ws[wid] = x;
    __syncthreads();
    if (wid == 0) {
        int w = ws[lane];
#pragma unroll
        for (int o = 1; o < 32; o <<= 1) {
            int u = __shfl_up_sync(0xffffffffu, w, o);
            if (lane >= o) w += u;
        }
        ws[lane] = w;
    }
    __syncthreads();
    int excl = x - v + (wid > 0 ? ws[wid - 1] : 0) + g_bsum[blockIdx.x];
    if (i < N) {
        g_rs[i]  = excl;
        g_cur[i] = excl;
        g_dinv[i] = rsqrtf((float)(v + 1));   // +1 self loop
    }
    if (i == 0) g_rs[N] = E;
}

// ---------------- scatter: build CSR column array ----------------
__global__ void scatter_kernel(const void* __restrict__ ei, int E) {
    int e = blockIdx.x * blockDim.x + threadIdx.x;
    if (e >= E) return;
    int is64 = g_is64;
    int s = get_idx(ei, e, is64);
    int d = get_idx(ei, (long long)E + e, is64);
    int pos = atomicAdd(&g_cur[d], 1);
    g_col[pos] = s;
}

// ---------------- tiled fp32 GEMM with fused row-scale: C = dinv[r]*(A@B) ----
template <int BM, int BN, int BK, int TM, int TN>
__global__ void gemm_kernel(const float* __restrict__ A,
                            const float* __restrict__ B,
                            float* __restrict__ C, int M, int K) {
    constexpr int NT  = (BM / TM) * (BN / TN);
    constexpr int LDA = BM + 4;
    __shared__ float As[BK * LDA];   // transposed: As[k][row]
    __shared__ float Bs[BK * BN];    // Bs[k][col]

    const int tid = threadIdx.x;
    const int tx  = tid % (BN / TN);
    const int ty  = tid / (BN / TN);
    const int row0 = blockIdx.x * BM;

    float acc[TM][TN];
#pragma unroll
    for (int i = 0; i < TM; i++)
#pragma unroll
        for (int j = 0; j < TN; j++) acc[i][j] = 0.0f;

    for (int k0 = 0; k0 < K; k0 += BK) {
        for (int idx = tid; idx < BM * BK; idx += NT) {
            int r = idx / BK, kk = idx % BK;
            int gr = row0 + r;
            As[kk * LDA + r] = (gr < M) ? A[(size_t)gr * K + k0 + kk] : 0.0f;
        }
        for (int idx = tid; idx < BK * BN; idx += NT) {
            int kk = idx / BN, c = idx % BN;
            Bs[kk * BN + c] = B[(size_t)(k0 + kk) * BN + c];
        }
        __syncthreads();
#pragma unroll
        for (int kk = 0; kk < BK; kk++) {
            float a[TM], b[TN];
#pragma unroll
            for (int i = 0; i < TM; i++) a[i] = As[kk * LDA + ty * TM + i];
#pragma unroll
            for (int j = 0; j < TN; j++) b[j] = Bs[kk * BN + tx * TN + j];
#pragma unroll
            for (int i = 0; i < TM; i++)
#pragma unroll
                for (int j = 0; j < TN; j++) acc[i][j] += a[i] * b[j];
        }
        __syncthreads();
    }

#pragma unroll
    for (int i = 0; i < TM; i++) {
        int gr = row0 + ty * TM + i;
        if (gr < M) {
            float di = g_dinv[gr];
#pragma unroll
            for (int j = 0; j < TN; j++)
                C[(size_t)gr * BN + tx * TN + j] = acc[i][j] * di;
        }
    }
}

// ---------------- layer-1 aggregation (warp/node, dual-acc ILP) -------------
__global__ void __launch_bounds__(256) agg1_kernel(const float* __restrict__ b1, int N) {
    int warp = (blockIdx.x * blockDim.x + threadIdx.x) >> 5;
    int lane = threadIdx.x & 31;
    if (warp >= N) return;
    int d = warp;
    const float4* __restrict__ yw4 = (const float4*)g_yw;

    float4 acc0 = yw4[(size_t)d * 32 + lane];     // self-loop (pre-scaled)
    float4 acc1 = make_float4(0.f, 0.f, 0.f, 0.f);
    int s0 = g_rs[d], s1 = g_rs[d + 1];
    for (int base = s0; base < s1; base += 32) {
        int n = s1 - base; if (n > 32) n = 32;
        int c = (lane < n) ? g_col[base + lane] : 0;
        int j = 0;
#pragma unroll 4
        for (; j + 2 <= n; j += 2) {
            int sa = __shfl_sync(0xffffffffu, c, j);
            int sb = __shfl_sync(0xffffffffu, c, j + 1);
            float4 va = yw4[(size_t)sa * 32 + lane];
            float4 vb = yw4[(size_t)sb * 32 + lane];
            acc0.x += va.x; acc0.y += va.y; acc0.z += va.z; acc0.w += va.w;
            acc1.x += vb.x; acc1.y += vb.y; acc1.z += vb.z; acc1.w += vb.w;
        }
        if (j < n) {
            int sa = __shfl_sync(0xffffffffu, c, j);
            float4 va = yw4[(size_t)sa * 32 + lane];
            acc0.x += va.x; acc0.y += va.y; acc0.z += va.z; acc0.w += va.w;
        }
    }
    float di = g_dinv[d];
    float4 bb = ((const float4*)b1)[lane];
    float4 o;
    o.x = fmaxf((acc0.x + acc1.x) * di + bb.x, 0.0f);
    o.y = fmaxf((acc0.y + acc1.y) * di + bb.y, 0.0f);
    o.z = fmaxf((acc0.z + acc1.z) * di + bb.z, 0.0f);
    o.w = fmaxf((acc0.w + acc1.w) * di + bb.w, 0.0f);
    ((float4*)g_h)[(size_t)d * 32 + lane] = o;
}

// ---------------- layer-2 aggregation + bias + softmax (warp/node) ----------
// 10 lanes x float4 cover the 40-wide row. Lanes >= 10 idle on loads but
// participate in shfl index broadcast and warp reductions.
__global__ void __launch_bounds__(256) agg2_kernel(float* __restrict__ out,
                                                   const float* __restrict__ b2, int N) {
    int warp = (blockIdx.x * blockDim.x + threadIdx.x) >> 5;
    int lane = threadIdx.x & 31;
    if (warp >= N) return;
    int d = warp;
    const float4* __restrict__ ow4 = (const float4*)g_ow;   // row = 10 float4

    bool act = (lane < 10);
    float4 acc0 = act ? ow4[(size_t)d * 10 + lane] : make_float4(0.f, 0.f, 0.f, 0.f);
    float4 acc1 = make_float4(0.f, 0.f, 0.f, 0.f);

    int s0 = g_rs[d], s1 = g_rs[d + 1];
    for (int base = s0; base < s1; base += 32) {
        int n = s1 - base; if (n > 32) n = 32;
        int c = (lane < n) ? g_col[base + lane] : 0;
        int j = 0;
#pragma unroll 4
        for (; j + 2 <= n; j += 2) {
            int sa = __shfl_sync(0xffffffffu, c, j);
            int sb = __shfl_sync(0xffffffffu, c, j + 1);
            if (act) {
                float4 va = ow4[(size_t)sa * 10 + lane];
                float4 vb = ow4[(size_t)sb * 10 + lane];
                acc0.x += va.x; acc0.y += va.y; acc0.z += va.z; acc0.w += va.w;
                acc1.x += vb.x; acc1.y += vb.y; acc1.z += vb.z; acc1.w += vb.w;
            }
        }
        if (j < n) {
            int sa = __shfl_sync(0xffffffffu, c, j);
            if (act) {
                float4 va = ow4[(size_t)sa * 10 + lane];
                acc0.x += va.x; acc0.y += va.y; acc0.z += va.z; acc0.w += va.w;
            }
        }
    }

    float di = g_dinv[d];
    float4 l = make_float4(-1e30f, -1e30f, -1e30f, -1e30f);
    if (act) {
        float4 bb = ((const float4*)b2)[lane];
        l.x = (acc0.x + acc1.x) * di + bb.x;
        l.y = (acc0.y + acc1.y) * di + bb.y;
        l.z = (acc0.z + acc1.z) * di + bb.z;
        l.w = (acc0.w + acc1.w) * di + bb.w;
    }
    float m = fmaxf(fmaxf(l.x, l.y), fmaxf(l.z, l.w));
#pragma unroll
    for (int o = 16; o > 0; o >>= 1)
        m = fmaxf(m, __shfl_xor_sync(0xffffffffu, m, o));
    float4 e;
    e.x = __expf(l.x - m); e.y = __expf(l.y - m);
    e.z = __expf(l.z - m); e.w = __expf(l.w - m);
    float s = act ? (e.x + e.y + e.z + e.w) : 0.0f;
#pragma unroll
    for (int o = 16; o > 0; o >>= 1)
        s += __shfl_xor_sync(0xffffffffu, s, o);
    float inv = 1.0f / s;
    if (act) {
        float4 w;
        w.x = e.x * inv; w.y = e.y * inv; w.z = e.z * inv; w.w = e.w * inv;
        ((float4*)out)[(size_t)d * 10 + lane] = w;
    }
}

// ---------------- launch ----------------
extern "C" void kernel_launch(void* const* d_in, const int* in_sizes, int n_in,
                              void* d_out, int out_size) {
    const float* x  = (const float*)d_in[0];
    const void*  ei = d_in[1];
    const float* W1 = (const float*)d_in[2];
    const float* b1 = (const float*)d_in[3];
    const float* W2 = (const float*)d_in[4];
    const float* b2 = (const float*)d_in[5];
    float* out = (float*)d_out;

    int N = in_sizes[0] / IN_DIM;
    int E = in_sizes[1] / 2;
    int nb = (N + SCAN_B - 1) / SCAN_B;

    float *yw, *h, *ow;
    cudaGetSymbolAddress((void**)&yw, g_yw);
    cudaGetSymbolAddress((void**)&h,  g_h);
    cudaGetSymbolAddress((void**)&ow, g_ow);

    // CSR build (scatter deferred past gemm1 — only agg1 needs g_col)
    detzero_kernel<<<(N + 255) / 256, 256>>>((const int*)ei, 2 * E, N);   // 1
    deg_kernel<<<(E + 255) / 256, 256>>>(ei, E);                          // 2
    scan_p1_kernel<<<nb, SCAN_B>>>(N);                                    // 3
    scan_p2_kernel<<<1, 1024>>>(nb);                                      // 4
    scan_p3_kernel<<<nb, SCAN_B>>>(N, E);                                 // 5

    // layer 1
    gemm_kernel<128, 128, 16, 8, 8><<<(N + 127) / 128, 256>>>(x, W1, yw, N, IN_DIM);  // 6 (ncu)
    scatter_kernel<<<(E + 255) / 256, 256>>>(ei, E);                      // 7
    agg1_kernel<<<(N * 32 + 255) / 256, 256>>>(b1, N);                    // 8

    // layer 2
    gemm_kernel<128, 40, 16, 8, 5><<<(N + 127) / 128, 128>>>(h, W2, ow, N, HIDD);     // 9
    agg2_kernel<<<(N * 32 + 255) / 256, 256>>>(out, b2, N);               // 10
}

// round 6
// speedup vs baseline: 2.0132x; 1.3862x over previous
#include <cuda_runtime.h>

#define IN_DIM 128
#define HIDD   128
#define OUTD   40
#define MAXN   50000
#define MAXE   800000
#define SCAN_B 256

// ---------------- scratch (device globals: allocation-free) ----------------
static __device__ float g_yw[MAXN * HIDD];    // dinv * (x @ W1)
static __device__ float g_h [MAXN * HIDD];    // layer-1 output (post ReLU)
static __device__ float g_ow[MAXN * OUTD];    // dinv * (h @ W2)
static __device__ int   g_degi[MAXN];         // edge in-degree (no self loop)
static __device__ float g_dinv[MAXN];
static __device__ int   g_rs  [MAXN + 1];     // CSR row starts
static __device__ int   g_cur [MAXN];         // scatter cursors
static __device__ int   g_col [MAXE];         // CSR column (src) indices
static __device__ int   g_bsum[(MAXN + SCAN_B - 1) / SCAN_B + 1];
static __device__ int   g_is64;               // edge_index dtype flag

// ---------------- fused: dtype detection (block 0) + zero degrees ----------
__global__ void detzero_kernel(const int* __restrict__ ei, int twoE, int N) {
    int i = blockIdx.x * blockDim.x + threadIdx.x;
    if (i < N) g_degi[i] = 0;
    if (blockIdx.x == 0) {
        __shared__ int s_any;
        if (threadIdx.x == 0) s_any = 0;
        __syncthreads();
        int lim = twoE < 8192 ? twoE : 8192;
        for (int k = 1 + 2 * (int)threadIdx.x; k < lim; k += 2 * (int)blockDim.x)
            if (ei[k] != 0) s_any = 1;
        __syncthreads();
        if (threadIdx.x == 0) g_is64 = (s_any == 0) ? 1 : 0;
    }
}

__device__ __forceinline__ int get_idx(const void* ei, long long pos, int is64) {
    return is64 ? (int)((const long long*)ei)[pos] : ((const int*)ei)[pos];
}

// ---------------- degree histogram ----------------
__global__ void deg_kernel(const void* __restrict__ ei, int E) {
    int e = blockIdx.x * blockDim.x + threadIdx.x;
    if (e >= E) return;
    int d = get_idx(ei, (long long)E + e, g_is64);
    atomicAdd(&g_degi[d], 1);
}

// ---------------- parallel 3-phase exclusive scan ----------------
__global__ void scan_p1_kernel(int N) {
    int i = blockIdx.x * blockDim.x + threadIdx.x;
    int v = (i < N) ? g_degi[i] : 0;
    int lane = threadIdx.x & 31, wid = threadIdx.x >> 5;
#pragma unroll
    for (int o = 16; o > 0; o >>= 1) v += __shfl_xor_sync(0xffffffffu, v, o);
    __shared__ int ws[SCAN_B / 32];
    if (lane == 0) ws[wid] = v;
    __syncthreads();
    if (threadIdx.x == 0) {
        int s = 0;
#pragma unroll
        for (int w = 0; w < SCAN_B / 32; w++) s += ws[w];
        g_bsum[blockIdx.x] = s;
    }
}

__global__ void scan_p2_kernel(int nb) {
    int t = threadIdx.x;
    int v = (t < nb) ? g_bsum[t] : 0;
    int lane = t & 31, wid = t >> 5;
    int x = v;
#pragma unroll
    for (int o = 1; o < 32; o <<= 1) {
        int u = __shfl_up_sync(0xffffffffu, x, o);
        if (lane >= o) x += u;
    }
    __shared__ int ws[32];
    if (lane == 31) ws[wid] = x;
    __syncthreads();
    if (wid == 0) {
        int w = ws[lane];
#pragma unroll
        for (int o = 1; o < 32; o <<= 1) {
            int u = __shfl_up_sync(0xffffffffu, w, o);
            if (lane >= o) w += u;
        }
        ws[lane] = w;
    }
    __syncthreads();
    int excl = x - v + (wid > 0 ? ws[wid - 1] : 0);
    if (t < nb) g_bsum[t] = excl;
}

__global__ void scan_p3_kernel(int N, int E) {
    int i = blockIdx.x * blockDim.x + threadIdx.x;
    int v = (i < N) ? g_degi[i] : 0;
    int lane = threadIdx.x & 31, wid = threadIdx.x >> 5;

    __shared__ int ws[32];
    if (threadIdx.x < 32) ws[threadIdx.x] = 0;
    __syncthreads();

    int x = v;
#pragma unroll
    for (int o = 1; o < 32; o <<= 1) {
        int u = __shfl_up_sync(0xffffffffu, x, o);
        if (lane >= o) x += u;
    }
    if (lane == 31) ws[wid] = x;
    __syncthreads();
    if (wid == 0) {
        int w = ws[lane];
#pragma unroll
        for (int o = 1; o < 32; o <<= 1) {
            int u = __shfl_up_sync(0xffffffffu, w, o);
            if (lane >= o) w += u;
        }
        ws[lane] = w;
    }
    __syncthreads();
    int excl = x - v + (wid > 0 ? ws[wid - 1] : 0) + g_bsum[blockIdx.x];
    if (i < N) {
        g_rs[i]  = excl;
        g_cur[i] = excl;
        g_dinv[i] = rsqrtf((float)(v + 1));   // +1 self loop
    }
    if (i == 0) g_rs[N] = E;
}

// ---------------- scatter: build CSR column array ----------------
__global__ void scatter_kernel(const void* __restrict__ ei, int E) {
    int e = blockIdx.x * blockDim.x + threadIdx.x;
    if (e >= E) return;
    int is64 = g_is64;
    int s = get_idx(ei, e, is64);
    int d = get_idx(ei, (long long)E + e, is64);
    int pos = atomicAdd(&g_cur[d], 1);
    g_col[pos] = s;
}

// ---------------- TF32 tensor-core GEMM1: C = dinv[r] * (A[M,128] @ B[128,128])
__device__ __forceinline__ unsigned f2tf(float f) {
    unsigned u;
    asm("cvt.rna.tf32.f32 %0, %1;" : "=r"(u) : "f"(f));
    return u;
}

__global__ void __launch_bounds__(256) gemm1_tc_kernel(const float* __restrict__ A,
                                                       const float* __restrict__ B,
                                                       float* __restrict__ C, int M) {
    // block: 128 rows x 128 cols, 8 warps x 16 rows each, full N=128 per warp.
    __shared__ unsigned As[32][136];   // [k][row], pad 136 -> conflict-free frags
    __shared__ unsigned Bs[32][136];   // [k][n]

    const int tid  = threadIdx.x;
    const int wid  = tid >> 5;
    const int lane = tid & 31;
    const int g    = lane >> 2;        // group id (0..7)
    const int t    = lane & 3;         // thread-in-group (0..3)
    const int row0 = blockIdx.x * 128;

    float c[16][4];
#pragma unroll
    for (int j = 0; j < 16; j++)
#pragma unroll
        for (int q = 0; q < 4; q++) c[j][q] = 0.0f;

    for (int k0 = 0; k0 < 128; k0 += 32) {
        // stage A (transposed to [k][row]) and B ([k][n]), converted to tf32
#pragma unroll
        for (int f = 0; f < 4; f++) {
            int l4  = tid + f * 256;          // 0..1023 float4 slots
            int row = l4 >> 3;                // 0..127
            int kq  = (l4 & 7) * 4;           // 0,4,...,28
            float4 v = make_float4(0.f, 0.f, 0.f, 0.f);
            if (row0 + row < M)
                v = *(const float4*)(A + (size_t)(row0 + row) * 128 + k0 + kq);
            As[kq + 0][row] = f2tf(v.x);
            As[kq + 1][row] = f2tf(v.y);
            As[kq + 2][row] = f2tf(v.z);
            As[kq + 3][row] = f2tf(v.w);

            int bk = l4 >> 5;                 // 0..31
            int bn = (l4 & 31) * 4;           // 0..124
            float4 w = *(const float4*)(B + (size_t)(k0 + bk) * 128 + bn);
            Bs[bk][bn + 0] = f2tf(w.x);
            Bs[bk][bn + 1] = f2tf(w.y);
            Bs[bk][bn + 2] = f2tf(w.z);
            Bs[bk][bn + 3] = f2tf(w.w);
        }
        __syncthreads();

#pragma unroll
        for (int kk = 0; kk < 4; kk++) {
            unsigned a0 = As[kk * 8 + t    ][wid * 16 + g    ];
            unsigned a1 = As[kk * 8 + t    ][wid * 16 + g + 8];
            unsigned a2 = As[kk * 8 + t + 4][wid * 16 + g    ];
            unsigned a3 = As[kk * 8 + t + 4][wid * 16 + g + 8];
#pragma unroll
            for (int j = 0; j < 16; j++) {
                unsigned b0 = Bs[kk * 8 + t    ][j * 8 + g];
                unsigned b1 = Bs[kk * 8 + t + 4][j * 8 + g];
                asm volatile(
                    "mma.sync.aligned.m16n8k8.row.col.f32.tf32.tf32.f32 "
                    "{%0,%1,%2,%3}, {%4,%5,%6,%7}, {%8,%9}, {%0,%1,%2,%3};"
                    : "+f"(c[j][0]), "+f"(c[j][1]), "+f"(c[j][2]), "+f"(c[j][3])
                    : "r"(a0), "r"(a1), "r"(a2), "r"(a3), "r"(b0), "r"(b1));
            }
        }
        __syncthreads();
    }

    // epilogue: scale rows by dinv, float2 stores
    int r1 = row0 + wid * 16 + g;
    int r2 = r1 + 8;
    float d1 = (r1 < M) ? g_dinv[r1] : 0.0f;
    float d2 = (r2 < M) ? g_dinv[r2] : 0.0f;
#pragma unroll
    for (int j = 0; j < 16; j++) {
        int n = j * 8 + t * 2;
        if (r1 < M) {
            float2 v = make_float2(c[j][0] * d1, c[j][1] * d1);
            *(float2*)(C + (size_t)r1 * 128 + n) = v;
        }
        if (r2 < M) {
            float2 v = make_float2(c[j][2] * d2, c[j][3] * d2);
            *(float2*)(C + (size_t)r2 * 128 + n) = v;
        }
    }
}

// ---------------- tiled fp32 GEMM (layer 2): C = dinv[r]*(A@B) ----------
template <int BM, int BN, int BK, int TM, int TN>
__global__ void gemm_kernel(const float* __restrict__ A,
                            const float* __restrict__ B,
                            float* __restrict__ C, int M, int K) {
    constexpr int NT  = (BM / TM) * (BN / TN);
    constexpr int LDA = BM + 4;
    __shared__ float As[BK * LDA];   // transposed: As[k][row]
    __shared__ float Bs[BK * BN];    // Bs[k][col]

    const int tid = threadIdx.x;
    const int tx  = tid % (BN / TN);
    const int ty  = tid / (BN / TN);
    const int row0 = blockIdx.x * BM;

    float acc[TM][TN];
#pragma unroll
    for (int i = 0; i < TM; i++)
#pragma unroll
        for (int j = 0; j < TN; j++) acc[i][j] = 0.0f;

    for (int k0 = 0; k0 < K; k0 += BK) {
        for (int idx = tid; idx < BM * BK; idx += NT) {
            int r = idx / BK, kk = idx % BK;
            int gr = row0 + r;
            As[kk * LDA + r] = (gr < M) ? A[(size_t)gr * K + k0 + kk] : 0.0f;
        }
        for (int idx = tid; idx < BK * BN; idx += NT) {
            int kk = idx / BN, c = idx % BN;
            Bs[kk * BN + c] = B[(size_t)(k0 + kk) * BN + c];
        }
        __syncthreads();
#pragma unroll
        for (int kk = 0; kk < BK; kk++) {
            float a[TM], b[TN];
#pragma unroll
            for (int i = 0; i < TM; i++) a[i] = As[kk * LDA + ty * TM + i];
#pragma unroll
            for (int j = 0; j < TN; j++) b[j] = Bs[kk * BN + tx * TN + j];
#pragma unroll
            for (int i = 0; i < TM; i++)
#pragma unroll
                for (int j = 0; j < TN; j++) acc[i][j] += a[i] * b[j];
        }
        __syncthreads();
    }

#pragma unroll
    for (int i = 0; i < TM; i++) {
        int gr = row0 + ty * TM + i;
        if (gr < M) {
            float di = g_dinv[gr];
#pragma unroll
            for (int j = 0; j < TN; j++)
                C[(size_t)gr * BN + tx * TN + j] = acc[i][j] * di;
        }
    }
}

// ---------------- layer-1 aggregation (warp/node, dual-acc ILP) -------------
__global__ void __launch_bounds__(256) agg1_kernel(const float* __restrict__ b1, int N) {
    int warp = (blockIdx.x * blockDim.x + threadIdx.x) >> 5;
    int lane = threadIdx.x & 31;
    if (warp >= N) return;
    int d = warp;
    const float4* __restrict__ yw4 = (const float4*)g_yw;

    float4 acc0 = yw4[(size_t)d * 32 + lane];     // self-loop (pre-scaled)
    float4 acc1 = make_float4(0.f, 0.f, 0.f, 0.f);
    int s0 = g_rs[d], s1 = g_rs[d + 1];
    for (int base = s0; base < s1; base += 32) {
        int n = s1 - base; if (n > 32) n = 32;
        int c = (lane < n) ? g_col[base + lane] : 0;
        int j = 0;
#pragma unroll 4
        for (; j + 2 <= n; j += 2) {
            int sa = __shfl_sync(0xffffffffu, c, j);
            int sb = __shfl_sync(0xffffffffu, c, j + 1);
            float4 va = yw4[(size_t)sa * 32 + lane];
            float4 vb = yw4[(size_t)sb * 32 + lane];
            acc0.x += va.x; acc0.y += va.y; acc0.z += va.z; acc0.w += va.w;
            acc1.x += vb.x; acc1.y += vb.y; acc1.z += vb.z; acc1.w += vb.w;
        }
        if (j < n) {
            int sa = __shfl_sync(0xffffffffu, c, j);
            float4 va = yw4[(size_t)sa * 32 + lane];
            acc0.x += va.x; acc0.y += va.y; acc0.z += va.z; acc0.w += va.w;
        }
    }
    float di = g_dinv[d];
    float4 bb = ((const float4*)b1)[lane];
    float4 o;
    o.x = fmaxf((acc0.x + acc1.x) * di + bb.x, 0.0f);
    o.y = fmaxf((acc0.y + acc1.y) * di + bb.y, 0.0f);
    o.z = fmaxf((acc0.z + acc1.z) * di + bb.z, 0.0f);
    o.w = fmaxf((acc0.w + acc1.w) * di + bb.w, 0.0f);
    ((float4*)g_h)[(size_t)d * 32 + lane] = o;
}

// ---------------- layer-2 aggregation + bias + softmax (warp/node) ----------
__global__ void __launch_bounds__(256) agg2_kernel(float* __restrict__ out,
                                                   const float* __restrict__ b2, int N) {
    int warp = (blockIdx.x * blockDim.x + threadIdx.x) >> 5;
    int lane = threadIdx.x & 31;
    if (warp >= N) return;
    int d = warp;
    const float4* __restrict__ ow4 = (const float4*)g_ow;   // row = 10 float4

    bool act = (lane < 10);
    float4 acc0 = act ? ow4[(size_t)d * 10 + lane] : make_float4(0.f, 0.f, 0.f, 0.f);
    float4 acc1 = make_float4(0.f, 0.f, 0.f, 0.f);

    int s0 = g_rs[d], s1 = g_rs[d + 1];
    for (int base = s0; base < s1; base += 32) {
        int n = s1 - base; if (n > 32) n = 32;
        int c = (lane < n) ? g_col[base + lane] : 0;
        int j = 0;
#pragma unroll 4
        for (; j + 2 <= n; j += 2) {
            int sa = __shfl_sync(0xffffffffu, c, j);
            int sb = __shfl_sync(0xffffffffu, c, j + 1);
            if (act) {
                float4 va = ow4[(size_t)sa * 10 + lane];
                float4 vb = ow4[(size_t)sb * 10 + lane];
                acc0.x += va.x; acc0.y += va.y; acc0.z += va.z; acc0.w += va.w;
                acc1.x += vb.x; acc1.y += vb.y; acc1.z += vb.z; acc1.w += vb.w;
            }
        }
        if (j < n) {
            int sa = __shfl_sync(0xffffffffu, c, j);
            if (act) {
                float4 va = ow4[(size_t)sa * 10 + lane];
                acc0.x += va.x; acc0.y += va.y; acc0.z += va.z; acc0.w += va.w;
            }
        }
    }

    float di = g_dinv[d];
    float4 l = make_float4(-1e30f, -1e30f, -1e30f, -1e30f);
    if (act) {
        float4 bb = ((const float4*)b2)[lane];
        l.x = (acc0.x + acc1.x) * di + bb.x;
        l.y = (acc0.y + acc1.y) * di + bb.y;
        l.z = (acc0.z + acc1.z) * di + bb.z;
        l.w = (acc0.w + acc1.w) * di + bb.w;
    }
    float m = fmaxf(fmaxf(l.x, l.y), fmaxf(l.z, l.w));
#pragma unroll
    for (int o = 16; o > 0; o >>= 1)
        m = fmaxf(m, __shfl_xor_sync(0xffffffffu, m, o));
    float4 e;
    e.x = __expf(l.x - m); e.y = __expf(l.y - m);
    e.z = __expf(l.z - m); e.w = __expf(l.w - m);
    float s = act ? (e.x + e.y + e.z + e.w) : 0.0f;
#pragma unroll
    for (int o = 16; o > 0; o >>= 1)
        s += __shfl_xor_sync(0xffffffffu, s, o);
    float inv = 1.0f / s;
    if (act) {
        float4 w;
        w.x = e.x * inv; w.y = e.y * inv; w.z = e.z * inv; w.w = e.w * inv;
        ((float4*)out)[(size_t)d * 10 + lane] = w;
    }
}

// ---------------- launch ----------------
extern "C" void kernel_launch(void* const* d_in, const int* in_sizes, int n_in,
                              void* d_out, int out_size) {
    const float* x  = (const float*)d_in[0];
    const void*  ei = d_in[1];
    const float* W1 = (const float*)d_in[2];
    const float* b1 = (const float*)d_in[3];
    const float* W2 = (const float*)d_in[4];
    const float* b2 = (const float*)d_in[5];
    float* out = (float*)d_out;

    int N = in_sizes[0] / IN_DIM;
    int E = in_sizes[1] / 2;
    int nb = (N + SCAN_B - 1) / SCAN_B;

    float *yw, *h, *ow;
    cudaGetSymbolAddress((void**)&yw, g_yw);
    cudaGetSymbolAddress((void**)&h,  g_h);
    cudaGetSymbolAddress((void**)&ow, g_ow);

    // CSR build
    detzero_kernel<<<(N + 255) / 256, 256>>>((const int*)ei, 2 * E, N);
    deg_kernel<<<(E + 255) / 256, 256>>>(ei, E);
    scan_p1_kernel<<<nb, SCAN_B>>>(N);
    scan_p2_kernel<<<1, 1024>>>(nb);
    scan_p3_kernel<<<nb, SCAN_B>>>(N, E);

    // layer 1 (tensor-core tf32 GEMM)
    gemm1_tc_kernel<<<(N + 127) / 128, 256>>>(x, W1, yw, N);
    scatter_kernel<<<(E + 255) / 256, 256>>>(ei, E);
    agg1_kernel<<<(N * 32 + 255) / 256, 256>>>(b1, N);

    // layer 2
    gemm_kernel<128, 40, 16, 8, 5><<<(N + 127) / 128, 128>>>(h, W2, ow, N, HIDD);
    agg2_kernel<<<(N * 32 + 255) / 256, 256>>>(out, b2, N);
}

// round 7
// speedup vs baseline: 2.4473x; 1.2156x over previous
#include <cuda_runtime.h>
#include <cuda_fp16.h>

#define IN_DIM 128
#define HIDD   128
#define OUTD   40
#define MAXN   50000
#define MAXE   800000
#define SCAN_B 256

// ---------------- scratch (device globals: allocation-free) ----------------
static __device__ __half g_ywh[MAXN * HIDD];  // fp16: dinv * (x @ W1)
static __device__ float  g_h [MAXN * HIDD];   // fp32: layer-1 output (post ReLU)
static __device__ __half g_owh[MAXN * OUTD];  // fp16: dinv * (h @ W2)
static __device__ int    g_degi[MAXN];
static __device__ float  g_dinv[MAXN];
static __device__ int    g_rs  [MAXN + 1];
static __device__ int    g_cur [MAXN];
static __device__ int    g_col [MAXE];
static __device__ int    g_bsum[(MAXN + SCAN_B - 1) / SCAN_B + 1];
static __device__ int    g_is64;

// ---------------- fused: dtype detection (block 0) + zero degrees ----------
__global__ void detzero_kernel(const int* __restrict__ ei, int twoE, int N) {
    int i = blockIdx.x * blockDim.x + threadIdx.x;
    if (i < N) g_degi[i] = 0;
    if (blockIdx.x == 0) {
        __shared__ int s_any;
        if (threadIdx.x == 0) s_any = 0;
        __syncthreads();
        int lim = twoE < 8192 ? twoE : 8192;
        for (int k = 1 + 2 * (int)threadIdx.x; k < lim; k += 2 * (int)blockDim.x)
            if (ei[k] != 0) s_any = 1;
        __syncthreads();
        if (threadIdx.x == 0) g_is64 = (s_any == 0) ? 1 : 0;
    }
}

__device__ __forceinline__ int get_idx(const void* ei, long long pos, int is64) {
    return is64 ? (int)((const long long*)ei)[pos] : ((const int*)ei)[pos];
}

// ---------------- degree histogram ----------------
__global__ void deg_kernel(const void* __restrict__ ei, int E) {
    int e = blockIdx.x * blockDim.x + threadIdx.x;
    if (e >= E) return;
    int d = get_idx(ei, (long long)E + e, g_is64);
    atomicAdd(&g_degi[d], 1);
}

// ---------------- parallel 3-phase exclusive scan ----------------
__global__ void scan_p1_kernel(int N) {
    int i = blockIdx.x * blockDim.x + threadIdx.x;
    int v = (i < N) ? g_degi[i] : 0;
    int lane = threadIdx.x & 31, wid = threadIdx.x >> 5;
#pragma unroll
    for (int o = 16; o > 0; o >>= 1) v += __shfl_xor_sync(0xffffffffu, v, o);
    __shared__ int ws[SCAN_B / 32];
    if (lane == 0) ws[wid] = v;
    __syncthreads();
    if (threadIdx.x == 0) {
        int s = 0;
#pragma unroll
        for (int w = 0; w < SCAN_B / 32; w++) s += ws[w];
        g_bsum[blockIdx.x] = s;
    }
}

__global__ void scan_p2_kernel(int nb) {
    int t = threadIdx.x;
    int v = (t < nb) ? g_bsum[t] : 0;
    int lane = t & 31, wid = t >> 5;
    int x = v;
#pragma unroll
    for (int o = 1; o < 32; o <<= 1) {
        int u = __shfl_up_sync(0xffffffffu, x, o);
        if (lane >= o) x += u;
    }
    __shared__ int ws[32];
    if (lane == 31) ws[wid] = x;
    __syncthreads();
    if (wid == 0) {
        int w = ws[lane];
#pragma unroll
        for (int o = 1; o < 32; o <<= 1) {
            int u = __shfl_up_sync(0xffffffffu, w, o);
            if (lane >= o) w += u;
        }
        ws[lane] = w;
    }
    __syncthreads();
    int excl = x - v + (wid > 0 ? ws[wid - 1] : 0);
    if (t < nb) g_bsum[t] = excl;
}

__global__ void scan_p3_kernel(int N, int E) {
    int i = blockIdx.x * blockDim.x + threadIdx.x;
    int v = (i < N) ? g_degi[i] : 0;
    int lane = threadIdx.x & 31, wid = threadIdx.x >> 5;

    __shared__ int ws[32];
    if (threadIdx.x < 32) ws[threadIdx.x] = 0;
    __syncthreads();

    int x = v;
#pragma unroll
    for (int o = 1; o < 32; o <<= 1) {
        int u = __shfl_up_sync(0xffffffffu, x, o);
        if (lane >= o) x += u;
    }
    if (lane == 31) ws[wid] = x;
    __syncthreads();
    if (wid == 0) {
        int w = ws[lane];
#pragma unroll
        for (int o = 1; o < 32; o <<= 1) {
            int u = __shfl_up_sync(0xffffffffu, w, o);
            if (lane >= o) w += u;
        }
        ws[lane] = w;
    }
    __syncthreads();
    int excl = x - v + (wid > 0 ? ws[wid - 1] : 0) + g_bsum[blockIdx.x];
    if (i < N) {
        g_rs[i]  = excl;
        g_cur[i] = excl;
        g_dinv[i] = rsqrtf((float)(v + 1));
    }
    if (i == 0) g_rs[N] = E;
}

// ---------------- scatter: build CSR column array ----------------
__global__ void scatter_kernel(const void* __restrict__ ei, int E) {
    int e = blockIdx.x * blockDim.x + threadIdx.x;
    if (e >= E) return;
    int is64 = g_is64;
    int s = get_idx(ei, e, is64);
    int d = get_idx(ei, (long long)E + e, is64);
    int pos = atomicAdd(&g_cur[d], 1);
    g_col[pos] = s;
}

// ---------------- tf32 helpers ----------------
__device__ __forceinline__ unsigned f2tf(float f) {
    unsigned u;
    asm("cvt.rna.tf32.f32 %0, %1;" : "=r"(u) : "f"(f));
    return u;
}

// ---------------- TF32 GEMM1: g_ywh = half( dinv[r] * (A[M,128] @ B[128,128]) )
__global__ void __launch_bounds__(256) gemm1_tc_kernel(const float* __restrict__ A,
                                                       const float* __restrict__ B,
                                                       __half* __restrict__ C, int M) {
    __shared__ unsigned As[32][136];   // [k][row]
    __shared__ unsigned Bs[32][136];   // [k][n]

    const int tid  = threadIdx.x;
    const int wid  = tid >> 5;
    const int lane = tid & 31;
    const int g    = lane >> 2;
    const int t    = lane & 3;
    const int row0 = blockIdx.x * 128;

    float c[16][4];
#pragma unroll
    for (int j = 0; j < 16; j++)
#pragma unroll
        for (int q = 0; q < 4; q++) c[j][q] = 0.0f;

    for (int k0 = 0; k0 < 128; k0 += 32) {
#pragma unroll
        for (int f = 0; f < 4; f++) {
            int l4  = tid + f * 256;
            int row = l4 >> 3;
            int kq  = (l4 & 7) * 4;
            float4 v = make_float4(0.f, 0.f, 0.f, 0.f);
            if (row0 + row < M)
                v = *(const float4*)(A + (size_t)(row0 + row) * 128 + k0 + kq);
            As[kq + 0][row] = f2tf(v.x);
            As[kq + 1][row] = f2tf(v.y);
            As[kq + 2][row] = f2tf(v.z);
            As[kq + 3][row] = f2tf(v.w);

            int bk = l4 >> 5;
            int bn = (l4 & 31) * 4;
            float4 w = *(const float4*)(B + (size_t)(k0 + bk) * 128 + bn);
            Bs[bk][bn + 0] = f2tf(w.x);
            Bs[bk][bn + 1] = f2tf(w.y);
            Bs[bk][bn + 2] = f2tf(w.z);
            Bs[bk][bn + 3] = f2tf(w.w);
        }
        __syncthreads();

#pragma unroll
        for (int kk = 0; kk < 4; kk++) {
            unsigned a0 = As[kk * 8 + t    ][wid * 16 + g    ];
            unsigned a1 = As[kk * 8 + t    ][wid * 16 + g + 8];
            unsigned a2 = As[kk * 8 + t + 4][wid * 16 + g    ];
            unsigned a3 = As[kk * 8 + t + 4][wid * 16 + g + 8];
#pragma unroll
            for (int j = 0; j < 16; j++) {
                unsigned b0 = Bs[kk * 8 + t    ][j * 8 + g];
                unsigned b1 = Bs[kk * 8 + t + 4][j * 8 + g];
                asm volatile(
                    "mma.sync.aligned.m16n8k8.row.col.f32.tf32.tf32.f32 "
                    "{%0,%1,%2,%3}, {%4,%5,%6,%7}, {%8,%9}, {%0,%1,%2,%3};"
                    : "+f"(c[j][0]), "+f"(c[j][1]), "+f"(c[j][2]), "+f"(c[j][3])
                    : "r"(a0), "r"(a1), "r"(a2), "r"(a3), "r"(b0), "r"(b1));
            }
        }
        __syncthreads();
    }

    int r1 = row0 + wid * 16 + g;
    int r2 = r1 + 8;
    float d1 = (r1 < M) ? g_dinv[r1] : 0.0f;
    float d2 = (r2 < M) ? g_dinv[r2] : 0.0f;
#pragma unroll
    for (int j = 0; j < 16; j++) {
        int n = j * 8 + t * 2;
        if (r1 < M)
            *(__half2*)(C + (size_t)r1 * 128 + n) = __floats2half2_rn(c[j][0] * d1, c[j][1] * d1);
        if (r2 < M)
            *(__half2*)(C + (size_t)r2 * 128 + n) = __floats2half2_rn(c[j][2] * d2, c[j][3] * d2);
    }
}

// ---------------- TF32 GEMM2: g_owh = half( dinv[r] * (h[M,128] @ W2[128,40]) )
__global__ void __launch_bounds__(256) gemm2_tc_kernel(const float* __restrict__ A,
                                                       const float* __restrict__ B,
                                                       __half* __restrict__ C, int M) {
    __shared__ unsigned As[32][136];   // [k][row], per 32-k chunk
    __shared__ unsigned Bs[128][48];   // full B [k][n], staged once

    const int tid  = threadIdx.x;
    const int wid  = tid >> 5;
    const int lane = tid & 31;
    const int g    = lane >> 2;
    const int t    = lane & 3;
    const int row0 = blockIdx.x * 128;

    for (int i = tid; i < 128 * OUTD; i += 256) {
        int k = i / OUTD, n = i - k * OUTD;
        Bs[k][n] = f2tf(B[(size_t)k * OUTD + n]);
    }

    float c[5][4];
#pragma unroll
    for (int j = 0; j < 5; j++)
#pragma unroll
        for (int q = 0; q < 4; q++) c[j][q] = 0.0f;

    for (int k0 = 0; k0 < 128; k0 += 32) {
#pragma unroll
        for (int f = 0; f < 4; f++) {
            int l4  = tid + f * 256;
            int row = l4 >> 3;
            int kq  = (l4 & 7) * 4;
            float4 v = make_float4(0.f, 0.f, 0.f, 0.f);
            if (row0 + row < M)
                v = *(const float4*)(A + (size_t)(row0 + row) * 128 + k0 + kq);
            As[kq + 0][row] = f2tf(v.x);
            As[kq + 1][row] = f2tf(v.y);
            As[kq + 2][row] = f2tf(v.z);
            As[kq + 3][row] = f2tf(v.w);
        }
        __syncthreads();

#pragma unroll
        for (int kk = 0; kk < 4; kk++) {
            unsigned a0 = As[kk * 8 + t    ][wid * 16 + g    ];
            unsigned a1 = As[kk * 8 + t    ][wid * 16 + g + 8];
            unsigned a2 = As[kk * 8 + t + 4][wid * 16 + g    ];
            unsigned a3 = As[kk * 8 + t + 4][wid * 16 + g + 8];
#pragma unroll
            for (int j = 0; j < 5; j++) {
                unsigned b0 = Bs[k0 + kk * 8 + t    ][j * 8 + g];
                unsigned b1 = Bs[k0 + kk * 8 + t + 4][j * 8 + g];
                asm volatile(
                    "mma.sync.aligned.m16n8k8.row.col.f32.tf32.tf32.f32 "
                    "{%0,%1,%2,%3}, {%4,%5,%6,%7}, {%8,%9}, {%0,%1,%2,%3};"
                    : "+f"(c[j][0]), "+f"(c[j][1]), "+f"(c[j][2]), "+f"(c[j][3])
                    : "r"(a0), "r"(a1), "r"(a2), "r"(a3), "r"(b0), "r"(b1));
            }
        }
        __syncthreads();
    }

    int r1 = row0 + wid * 16 + g;
    int r2 = r1 + 8;
    float d1 = (r1 < M) ? g_dinv[r1] : 0.0f;
    float d2 = (r2 < M) ? g_dinv[r2] : 0.0f;
#pragma unroll
    for (int j = 0; j < 5; j++) {
        int n = j * 8 + t * 2;
        if (r1 < M)
            *(__half2*)(C + (size_t)r1 * OUTD + n) = __floats2half2_rn(c[j][0] * d1, c[j][1] * d1);
        if (r2 < M)
            *(__half2*)(C + (size_t)r2 * OUTD + n) = __floats2half2_rn(c[j][2] * d2, c[j][3] * d2);
    }
}

// ---------------- layer-1 aggregation (warp/node, fp16 gather, fp32 acc) ----
__global__ void __launch_bounds__(256) agg1_kernel(const float* __restrict__ b1, int N) {
    int warp = (blockIdx.x * blockDim.x + threadIdx.x) >> 5;
    int lane = threadIdx.x & 31;
    if (warp >= N) return;
    int d = warp;
    const __half* __restrict__ yw = g_ywh;

    // self-loop term: 4 halves per lane
    uint2 u = *(const uint2*)(yw + (size_t)d * 128 + lane * 4);
    float2 f0 = __half22float2(*(__half2*)&u.x);
    float2 f1 = __half22float2(*(__half2*)&u.y);
    float4 acc = make_float4(f0.x, f0.y, f1.x, f1.y);

    int s0 = g_rs[d], s1 = g_rs[d + 1];
    for (int base = s0; base < s1; base += 32) {
        int n = s1 - base; if (n > 32) n = 32;
        int c = (lane < n) ? g_col[base + lane] : 0;
#pragma unroll 4
        for (int j = 0; j < n; j++) {
            int s = __shfl_sync(0xffffffffu, c, j);
            uint2 v = *(const uint2*)(yw + (size_t)s * 128 + lane * 4);
            float2 a = __half22float2(*(__half2*)&v.x);
            float2 b = __half22float2(*(__half2*)&v.y);
            acc.x += a.x; acc.y += a.y; acc.z += b.x; acc.w += b.y;
        }
    }
    float di = g_dinv[d];
    float4 bb = *(const float4*)(b1 + lane * 4);
    float4 o;
    o.x = fmaxf(acc.x * di + bb.x, 0.0f);
    o.y = fmaxf(acc.y * di + bb.y, 0.0f);
    o.z = fmaxf(acc.z * di + bb.z, 0.0f);
    o.w = fmaxf(acc.w * di + bb.w, 0.0f);
    *(float4*)(g_h + (size_t)d * 128 + lane * 4) = o;
}

// ---------------- layer-2 aggregation + bias + softmax (warp/node, fp16) ----
__global__ void __launch_bounds__(256) agg2_kernel(float* __restrict__ out,
                                                   const float* __restrict__ b2, int N) {
    int warp = (blockIdx.x * blockDim.x + threadIdx.x) >> 5;
    int lane = threadIdx.x & 31;
    if (warp >= N) return;
    int d = warp;
    const __half* __restrict__ ow = g_owh;

    bool act = (lane < 10);
    float4 acc = make_float4(0.f, 0.f, 0.f, 0.f);
    if (act) {
        uint2 u = *(const uint2*)(ow + (size_t)d * OUTD + lane * 4);
        float2 f0 = __half22float2(*(__half2*)&u.x);
        float2 f1 = __half22float2(*(__half2*)&u.y);
        acc = make_float4(f0.x, f0.y, f1.x, f1.y);
    }

    int s0 = g_rs[d], s1 = g_rs[d + 1];
    for (int base = s0; base < s1; base += 32) {
        int n = s1 - base; if (n > 32) n = 32;
        int c = (lane < n) ? g_col[base + lane] : 0;
#pragma unroll 4
        for (int j = 0; j < n; j++) {
            int s = __shfl_sync(0xffffffffu, c, j);
            if (act) {
                uint2 v = *(const uint2*)(ow + (size_t)s * OUTD + lane * 4);
                float2 a = __half22float2(*(__half2*)&v.x);
                float2 b = __half22float2(*(__half2*)&v.y);
                acc.x += a.x; acc.y += a.y; acc.z += b.x; acc.w += b.y;
            }
        }
    }

    float di = g_dinv[d];
    float4 l = make_float4(-1e30f, -1e30f, -1e30f, -1e30f);
    if (act) {
        float4 bb = *(const float4*)(b2 + lane * 4);
        l.x = acc.x * di + bb.x;
        l.y = acc.y * di + bb.y;
        l.z = acc.z * di + bb.z;
        l.w = acc.w * di + bb.w;
    }
    float m = fmaxf(fmaxf(l.x, l.y), fmaxf(l.z, l.w));
#pragma unroll
    for (int o = 16; o > 0; o >>= 1)
        m = fmaxf(m, __shfl_xor_sync(0xffffffffu, m, o));
    float4 e;
    e.x = __expf(l.x - m); e.y = __expf(l.y - m);
    e.z = __expf(l.z - m); e.w = __expf(l.w - m);
    float s = act ? (e.x + e.y + e.z + e.w) : 0.0f;
#pragma unroll
    for (int o = 16; o > 0; o >>= 1)
        s += __shfl_xor_sync(0xffffffffu, s, o);
    float inv = 1.0f / s;
    if (act) {
        float4 w;
        w.x = e.x * inv; w.y = e.y * inv; w.z = e.z * inv; w.w = e.w * inv;
        *(float4*)(out + (size_t)d * OUTD + lane * 4) = w;
    }
}

// ---------------- launch ----------------
extern "C" void kernel_launch(void* const* d_in, const int* in_sizes, int n_in,
                              void* d_out, int out_size) {
    const float* x  = (const float*)d_in[0];
    const void*  ei = d_in[1];
    const float* W1 = (const float*)d_in[2];
    const float* b1 = (const float*)d_in[3];
    const float* W2 = (const float*)d_in[4];
    const float* b2 = (const float*)d_in[5];
    float* out = (float*)d_out;

    int N = in_sizes[0] / IN_DIM;
    int E = in_sizes[1] / 2;
    int nb = (N + SCAN_B - 1) / SCAN_B;

    __half *ywh, *owh;
    float *h;
    cudaGetSymbolAddress((void**)&ywh, g_ywh);
    cudaGetSymbolAddress((void**)&h,   g_h);
    cudaGetSymbolAddress((void**)&owh, g_owh);

    // CSR build
    detzero_kernel<<<(N + 255) / 256, 256>>>((const int*)ei, 2 * E, N);
    deg_kernel<<<(E + 255) / 256, 256>>>(ei, E);
    scan_p1_kernel<<<nb, SCAN_B>>>(N);
    scan_p2_kernel<<<1, 1024>>>(nb);
    scan_p3_kernel<<<nb, SCAN_B>>>(N, E);

    // layer 1
    gemm1_tc_kernel<<<(N + 127) / 128, 256>>>(x, W1, ywh, N);
    scatter_kernel<<<(E + 255) / 256, 256>>>(ei, E);
    agg1_kernel<<<(N * 32 + 255) / 256, 256>>>(b1, N);

    // layer 2
    gemm2_tc_kernel<<<(N + 127) / 128, 256>>>(h, W2, owh, N);
    agg2_kernel<<<(N * 32 + 255) / 256, 256>>>(out, b2, N);
}

// round 8
// speedup vs baseline: 2.5074x; 1.0246x over previous
#include <cuda_runtime.h>
#include <cuda_fp16.h>

#define IN_DIM 128
#define HIDD   128
#define OUTD   40
#define MAXN   50000
#define MAXE   800000
#define SCAN_B 256

// ---------------- scratch (device globals: allocation-free) ----------------
// g_degi is zero-initialized at module load and re-zeroed by scan_p3 each call
// (self-cleaning), so every graph replay sees a zeroed histogram.
static __device__ __half g_ywh[MAXN * HIDD];  // fp16: dinv * (x @ W1)
static __device__ float  g_h [MAXN * HIDD];   // fp32: layer-1 output (post ReLU)
static __device__ __half g_owh[MAXN * OUTD];  // fp16: dinv * (h @ W2)
static __device__ int    g_degi[MAXN];
static __device__ float  g_dinv[MAXN];
static __device__ int    g_rs  [MAXN + 1];
static __device__ int    g_cur [MAXN];
static __device__ int    g_col [MAXE];
static __device__ int    g_bsum[(MAXN + SCAN_B - 1) / SCAN_B + 1];

// ---------------- inline per-warp dtype detection ----------------
// int64 edge values < 2^31: odd 32-bit words (hi halves) are all zero.
// int32: odd words are random node ids -> ballot is nonzero w.p. ~1.
__device__ __forceinline__ int detect_is64_warp(const int* __restrict__ ei32) {
    int lane = threadIdx.x & 31;
    int v = ei32[1 + 2 * lane];          // first 64 words, odd positions
    unsigned any = __ballot_sync(0xffffffffu, v != 0);
    return any == 0 ? 1 : 0;
}

__device__ __forceinline__ int get_idx(const void* ei, long long pos, int is64) {
    return is64 ? (int)((const long long*)ei)[pos] : ((const int*)ei)[pos];
}

// ---------------- degree histogram (inline detect) ----------------
__global__ void deg_kernel(const void* __restrict__ ei, int E) {
    int is64 = detect_is64_warp((const int*)ei);
    int e = blockIdx.x * blockDim.x + threadIdx.x;
    if (e >= E) return;
    int d = get_idx(ei, (long long)E + e, is64);
    atomicAdd(&g_degi[d], 1);
}

// ---------------- scan phase 1: per-block sums ----------------
__global__ void scan_p1_kernel(int N) {
    int i = blockIdx.x * blockDim.x + threadIdx.x;
    int v = (i < N) ? g_degi[i] : 0;
    int lane = threadIdx.x & 31, wid = threadIdx.x >> 5;
#pragma unroll
    for (int o = 16; o > 0; o >>= 1) v += __shfl_xor_sync(0xffffffffu, v, o);
    __shared__ int ws[SCAN_B / 32];
    if (lane == 0) ws[wid] = v;
    __syncthreads();
    if (threadIdx.x == 0) {
        int s = 0;
#pragma unroll
        for (int w = 0; w < SCAN_B / 32; w++) s += ws[w];
        g_bsum[blockIdx.x] = s;
    }
}

// ---------------- scan phase 2+3 fused: block offset = reduce of prior bsums
__global__ void scan_p3_kernel(int N, int E) {
    int i = blockIdx.x * blockDim.x + threadIdx.x;
    int v = (i < N) ? g_degi[i] : 0;
    int lane = threadIdx.x & 31, wid = threadIdx.x >> 5;

    __shared__ int ws[32];
    __shared__ int s_off;
    if (threadIdx.x < 32) ws[threadIdx.x] = 0;
    if (threadIdx.x == 0) s_off = 0;
    __syncthreads();

    int x = v;
#pragma unroll
    for (int o = 1; o < 32; o <<= 1) {
        int u = __shfl_up_sync(0xffffffffu, x, o);
        if (lane >= o) x += u;
    }
    if (lane == 31) ws[wid] = x;
    __syncthreads();

    if (wid == 0) {                       // full warp: scan warp sums
        int w = ws[lane];
#pragma unroll
        for (int o = 1; o < 32; o <<= 1) {
            int u = __shfl_up_sync(0xffffffffu, w, o);
            if (lane >= o) w += u;
        }
        ws[lane] = w;
    } else if (wid == 1) {                // full warp: reduce prior block sums
        int off = 0;
        for (int j = lane; j < (int)blockIdx.x; j += 32) off += g_bsum[j];
#pragma unroll
        for (int o = 16; o > 0; o >>= 1)
            off += __shfl_xor_sync(0xffffffffu, off, o);
        if (lane == 0) s_off = off;
    }
    __syncthreads();

    int excl = x - v + (wid > 0 ? ws[wid - 1] : 0) + s_off;
    if (i < N) {
        g_rs[i]   = excl;
        g_cur[i]  = excl;
        g_dinv[i] = rsqrtf((float)(v + 1));   // +1 self loop
        g_degi[i] = 0;                        // self-clean for next replay
    }
    if (i == 0) g_rs[N] = E;
}

// ---------------- scatter: build CSR column array (inline detect) ----------
__global__ void scatter_kernel(const void* __restrict__ ei, int E) {
    int is64 = detect_is64_warp((const int*)ei);
    int e = blockIdx.x * blockDim.x + threadIdx.x;
    if (e >= E) return;
    int s = get_idx(ei, e, is64);
    int d = get_idx(ei, (long long)E + e, is64);
    int pos = atomicAdd(&g_cur[d], 1);
    g_col[pos] = s;
}

// ---------------- tf32 helpers ----------------
__device__ __forceinline__ unsigned f2tf(float f) {
    unsigned u;
    asm("cvt.rna.tf32.f32 %0, %1;" : "=r"(u) : "f"(f));
    return u;
}

// ---------------- TF32 GEMM1: g_ywh = half( dinv[r] * (A[M,128] @ B[128,128]) )
__global__ void __launch_bounds__(256) gemm1_tc_kernel(const float* __restrict__ A,
                                                       const float* __restrict__ B,
                                                       __half* __restrict__ C, int M) {
    __shared__ unsigned As[32][136];   // [k][row]
    __shared__ unsigned Bs[32][136];   // [k][n]

    const int tid  = threadIdx.x;
    const int wid  = tid >> 5;
    const int lane = tid & 31;
    const int g    = lane >> 2;
    const int t    = lane & 3;
    const int row0 = blockIdx.x * 128;

    float c[16][4];
#pragma unroll
    for (int j = 0; j < 16; j++)
#pragma unroll
        for (int q = 0; q < 4; q++) c[j][q] = 0.0f;

    for (int k0 = 0; k0 < 128; k0 += 32) {
#pragma unroll
        for (int f = 0; f < 4; f++) {
            int l4  = tid + f * 256;
            int row = l4 >> 3;
            int kq  = (l4 & 7) * 4;
            float4 v = make_float4(0.f, 0.f, 0.f, 0.f);
            if (row0 + row < M)
                v = *(const float4*)(A + (size_t)(row0 + row) * 128 + k0 + kq);
            As[kq + 0][row] = f2tf(v.x);
            As[kq + 1][row] = f2tf(v.y);
            As[kq + 2][row] = f2tf(v.z);
            As[kq + 3][row] = f2tf(v.w);

            int bk = l4 >> 5;
            int bn = (l4 & 31) * 4;
            float4 w = *(const float4*)(B + (size_t)(k0 + bk) * 128 + bn);
            Bs[bk][bn + 0] = f2tf(w.x);
            Bs[bk][bn + 1] = f2tf(w.y);
            Bs[bk][bn + 2] = f2tf(w.z);
            Bs[bk][bn + 3] = f2tf(w.w);
        }
        __syncthreads();

#pragma unroll
        for (int kk = 0; kk < 4; kk++) {
            unsigned a0 = As[kk * 8 + t    ][wid * 16 + g    ];
            unsigned a1 = As[kk * 8 + t    ][wid * 16 + g + 8];
            unsigned a2 = As[kk * 8 + t + 4][wid * 16 + g    ];
            unsigned a3 = As[kk * 8 + t + 4][wid * 16 + g + 8];
#pragma unroll
            for (int j = 0; j < 16; j++) {
                unsigned b0 = Bs[kk * 8 + t    ][j * 8 + g];
                unsigned b1 = Bs[kk * 8 + t + 4][j * 8 + g];
                asm volatile(
                    "mma.sync.aligned.m16n8k8.row.col.f32.tf32.tf32.f32 "
                    "{%0,%1,%2,%3}, {%4,%5,%6,%7}, {%8,%9}, {%0,%1,%2,%3};"
                    : "+f"(c[j][0]), "+f"(c[j][1]), "+f"(c[j][2]), "+f"(c[j][3])
                    : "r"(a0), "r"(a1), "r"(a2), "r"(a3), "r"(b0), "r"(b1));
            }
        }
        __syncthreads();
    }

    int r1 = row0 + wid * 16 + g;
    int r2 = r1 + 8;
    float d1 = (r1 < M) ? g_dinv[r1] : 0.0f;
    float d2 = (r2 < M) ? g_dinv[r2] : 0.0f;
#pragma unroll
    for (int j = 0; j < 16; j++) {
        int n = j * 8 + t * 2;
        if (r1 < M)
            *(__half2*)(C + (size_t)r1 * 128 + n) = __floats2half2_rn(c[j][0] * d1, c[j][1] * d1);
        if (r2 < M)
            *(__half2*)(C + (size_t)r2 * 128 + n) = __floats2half2_rn(c[j][2] * d2, c[j][3] * d2);
    }
}

// ---------------- TF32 GEMM2: g_owh = half( dinv[r] * (h[M,128] @ W2[128,40]) )
__global__ void __launch_bounds__(256) gemm2_tc_kernel(const float* __restrict__ A,
                                                       const float* __restrict__ B,
                                                       __half* __restrict__ C, int M) {
    __shared__ unsigned As[32][136];   // [k][row], per 32-k chunk
    __shared__ unsigned Bs[128][48];   // full B [k][n], staged once

    const int tid  = threadIdx.x;
    const int wid  = tid >> 5;
    const int lane = tid & 31;
    const int g    = lane >> 2;
    const int t    = lane & 3;
    const int row0 = blockIdx.x * 128;

    for (int i = tid; i < 128 * OUTD; i += 256) {
        int k = i / OUTD, n = i - k * OUTD;
        Bs[k][n] = f2tf(B[(size_t)k * OUTD + n]);
    }

    float c[5][4];
#pragma unroll
    for (int j = 0; j < 5; j++)
#pragma unroll
        for (int q = 0; q < 4; q++) c[j][q] = 0.0f;

    for (int k0 = 0; k0 < 128; k0 += 32) {
#pragma unroll
        for (int f = 0; f < 4; f++) {
            int l4  = tid + f * 256;
            int row = l4 >> 3;
            int kq  = (l4 & 7) * 4;
            float4 v = make_float4(0.f, 0.f, 0.f, 0.f);
            if (row0 + row < M)
                v = *(const float4*)(A + (size_t)(row0 + row) * 128 + k0 + kq);
            As[kq + 0][row] = f2tf(v.x);
            As[kq + 1][row] = f2tf(v.y);
            As[kq + 2][row] = f2tf(v.z);
            As[kq + 3][row] = f2tf(v.w);
        }
        __syncthreads();

#pragma unroll
        for (int kk = 0; kk < 4; kk++) {
            unsigned a0 = As[kk * 8 + t    ][wid * 16 + g    ];
            unsigned a1 = As[kk * 8 + t    ][wid * 16 + g + 8];
            unsigned a2 = As[kk * 8 + t + 4][wid * 16 + g    ];
            unsigned a3 = As[kk * 8 + t + 4][wid * 16 + g + 8];
#pragma unroll
            for (int j = 0; j < 5; j++) {
                unsigned b0 = Bs[k0 + kk * 8 + t    ][j * 8 + g];
                unsigned b1 = Bs[k0 + kk * 8 + t + 4][j * 8 + g];
                asm volatile(
                    "mma.sync.aligned.m16n8k8.row.col.f32.tf32.tf32.f32 "
                    "{%0,%1,%2,%3}, {%4,%5,%6,%7}, {%8,%9}, {%0,%1,%2,%3};"
                    : "+f"(c[j][0]), "+f"(c[j][1]), "+f"(c[j][2]), "+f"(c[j][3])
                    : "r"(a0), "r"(a1), "r"(a2), "r"(a3), "r"(b0), "r"(b1));
            }
        }
        __syncthreads();
    }

    int r1 = row0 + wid * 16 + g;
    int r2 = r1 + 8;
    float d1 = (r1 < M) ? g_dinv[r1] : 0.0f;
    float d2 = (r2 < M) ? g_dinv[r2] : 0.0f;
#pragma unroll
    for (int j = 0; j < 5; j++) {
        int n = j * 8 + t * 2;
        if (r1 < M)
            *(__half2*)(C + (size_t)r1 * OUTD + n) = __floats2half2_rn(c[j][0] * d1, c[j][1] * d1);
        if (r2 < M)
            *(__half2*)(C + (size_t)r2 * OUTD + n) = __floats2half2_rn(c[j][2] * d2, c[j][3] * d2);
    }
}

// ---------------- layer-1 aggregation (warp/node, fp16 gather, fp32 acc) ----
__global__ void __launch_bounds__(256) agg1_kernel(const float* __restrict__ b1, int N) {
    int warp = (blockIdx.x * blockDim.x + threadIdx.x) >> 5;
    int lane = threadIdx.x & 31;
    if (warp >= N) return;
    int d = warp;
    const __half* __restrict__ yw = g_ywh;

    uint2 u = *(const uint2*)(yw + (size_t)d * 128 + lane * 4);
    float2 f0 = __half22float2(*(__half2*)&u.x);
    float2 f1 = __half22float2(*(__half2*)&u.y);
    float4 acc = make_float4(f0.x, f0.y, f1.x, f1.y);

    int s0 = g_rs[d], s1 = g_rs[d + 1];
    for (int base = s0; base < s1; base += 32) {
        int n = s1 - base; if (n > 32) n = 32;
        int c = (lane < n) ? g_col[base + lane] : 0;
#pragma unroll 4
        for (int j = 0; j < n; j++) {
            int s = __shfl_sync(0xffffffffu, c, j);
            uint2 v = *(const uint2*)(yw + (size_t)s * 128 + lane * 4);
            float2 a = __half22float2(*(__half2*)&v.x);
            float2 b = __half22float2(*(__half2*)&v.y);
            acc.x += a.x; acc.y += a.y; acc.z += b.x; acc.w += b.y;
        }
    }
    float di = g_dinv[d];
    float4 bb = *(const float4*)(b1 + lane * 4);
    float4 o;
    o.x = fmaxf(acc.x * di + bb.x, 0.0f);
    o.y = fmaxf(acc.y * di + bb.y, 0.0f);
    o.z = fmaxf(acc.z * di + bb.z, 0.0f);
    o.w = fmaxf(acc.w * di + bb.w, 0.0f);
    *(float4*)(g_h + (size_t)d * 128 + lane * 4) = o;
}

// ---------------- layer-2 aggregation + bias + softmax (warp/node, fp16) ----
__global__ void __launch_bounds__(256) agg2_kernel(float* __restrict__ out,
                                                   const float* __restrict__ b2, int N) {
    int warp = (blockIdx.x * blockDim.x + threadIdx.x) >> 5;
    int lane = threadIdx.x & 31;
    if (warp >= N) return;
    int d = warp;
    const __half* __restrict__ ow = g_owh;

    bool act = (lane < 10);
    float4 acc = make_float4(0.f, 0.f, 0.f, 0.f);
    if (act) {
        uint2 u = *(const uint2*)(ow + (size_t)d * OUTD + lane * 4);
        float2 f0 = __half22float2(*(__half2*)&u.x);
        float2 f1 = __half22float2(*(__half2*)&u.y);
        acc = make_float4(f0.x, f0.y, f1.x, f1.y);
    }

    int s0 = g_rs[d], s1 = g_rs[d + 1];
    for (int base = s0; base < s1; base += 32) {
        int n = s1 - base; if (n > 32) n = 32;
        int c = (lane < n) ? g_col[base + lane] : 0;
#pragma unroll 4
        for (int j = 0; j < n; j++) {
            int s = __shfl_sync(0xffffffffu, c, j);
            if (act) {
                uint2 v = *(const uint2*)(ow + (size_t)s * OUTD + lane * 4);
                float2 a = __half22float2(*(__half2*)&v.x);
                float2 b = __half22float2(*(__half2*)&v.y);
                acc.x += a.x; acc.y += a.y; acc.z += b.x; acc.w += b.y;
            }
        }
    }

    float di = g_dinv[d];
    float4 l = make_float4(-1e30f, -1e30f, -1e30f, -1e30f);
    if (act) {
        float4 bb = *(const float4*)(b2 + lane * 4);
        l.x = acc.x * di + bb.x;
        l.y = acc.y * di + bb.y;
        l.z = acc.z * di + bb.z;
        l.w = acc.w * di + bb.w;
    }
    float m = fmaxf(fmaxf(l.x, l.y), fmaxf(l.z, l.w));
#pragma unroll
    for (int o = 16; o > 0; o >>= 1)
        m = fmaxf(m, __shfl_xor_sync(0xffffffffu, m, o));
    float4 e;
    e.x = __expf(l.x - m); e.y = __expf(l.y - m);
    e.z = __expf(l.z - m); e.w = __expf(l.w - m);
    float s = act ? (e.x + e.y + e.z + e.w) : 0.0f;
#pragma unroll
    for (int o = 16; o > 0; o >>= 1)
        s += __shfl_xor_sync(0xffffffffu, s, o);
    float inv = 1.0f / s;
    if (act) {
        float4 w;
        w.x = e.x * inv; w.y = e.y * inv; w.z = e.z * inv; w.w = e.w * inv;
        *(float4*)(out + (size_t)d * OUTD + lane * 4) = w;
    }
}

// ---------------- launch ----------------
extern "C" void kernel_launch(void* const* d_in, const int* in_sizes, int n_in,
                              void* d_out, int out_size) {
    const float* x  = (const float*)d_in[0];
    const void*  ei = d_in[1];
    const float* W1 = (const float*)d_in[2];
    const float* b1 = (const float*)d_in[3];
    const float* W2 = (const float*)d_in[4];
    const float* b2 = (const float*)d_in[5];
    float* out = (float*)d_out;

    int N = in_sizes[0] / IN_DIM;
    int E = in_sizes[1] / 2;
    int nb = (N + SCAN_B - 1) / SCAN_B;

    __half *ywh, *owh;
    float *h;
    cudaGetSymbolAddress((void**)&ywh, g_ywh);
    cudaGetSymbolAddress((void**)&h,   g_h);
    cudaGetSymbolAddress((void**)&owh, g_owh);

    // CSR build (8 launches total this call)
    deg_kernel<<<(E + 255) / 256, 256>>>(ei, E);            // 1
    scan_p1_kernel<<<nb, SCAN_B>>>(N);                      // 2
    scan_p3_kernel<<<nb, SCAN_B>>>(N, E);                   // 3 (fused p2+p3, self-clean)

    // layer 1
    gemm1_tc_kernel<<<(N + 127) / 128, 256>>>(x, W1, ywh, N);   // 4
    scatter_kernel<<<(E + 255) / 256, 256>>>(ei, E);            // 5
    agg1_kernel<<<(N * 32 + 255) / 256, 256>>>(b1, N);          // 6

    // layer 2
    gemm2_tc_kernel<<<(N + 127) / 128, 256>>>(h, W2, owh, N);   // 7
    agg2_kernel<<<(N * 32 + 255) / 256, 256>>>(out, b2, N);     // 8
}